// round 12
// baseline (speedup 1.0000x reference)
#include <cuda_runtime.h>
#include <cstdint>

// ============================================================================
// LinearDeepSeekV3: y = act_quant(x) @ dequant(weight)^T
// M=16384, N=256, K=7168, fp8 e4m3 weight with [128x128] block scales.
// Baseline-ISA (plain sm_103): legacy mma.sync.m16n8k32.e4m3, fp32 accum.
//
// R11: fused quant, latency hidden by prefetch.global.L2.
//  - R9 MMA mainloop kept verbatim (best measured config, 2 CTAs/SM).
//  - Quant fused back into the GEMM: during the MMA phase of chunk kc, each
//    thread issues an L2 prefetch for its 128B slice of x chunk kc+2 (zero
//    register cost). After the post-MMA barrier, quant loads hit L2, convert,
//    and STS into the just-freed A stage. No separate quant kernel, no fp8
//    activation round-trip through DRAM (saves ~590 MB of serial traffic).
// ============================================================================

#define KDIM 7168
#define NDIM 256
#define KC 128
#define KB 56
#define MT 64
#define NTH 256

// ---- gemm shared memory layout (bytes) ----
#define OFF_BS 0            // [2][256][128] u8 = 65536 (swizzled)
#define OFF_AS 65536        // [2][64][128] u8 = 16384 (swizzled)
#define OFF_SC 81920        // [2][64] f32 = 512
#define OFF_WS 82432        // [112] f32 = 448
#define SMEM_TOTAL 82880

__device__ __align__(16) uint8_t g_w8[(size_t)NDIM * KDIM];

__device__ __forceinline__ uint32_t smem_u32(const void* p) {
    uint32_t a;
    asm("{ .reg .u64 t; cvta.to.shared.u64 t, %1; cvt.u32.u64 %0, t; }" : "=r"(a) : "l"(p));
    return a;
}

#define CP_ASYNC16(dst, src) \
    asm volatile("cp.async.cg.shared.global [%0], [%1], 16;" :: "r"(dst), "l"(src) : "memory")

#define LDMATRIX_X4(r0, r1, r2, r3, addr) \
    asm volatile("ldmatrix.sync.aligned.m8n8.x4.shared.b16 {%0,%1,%2,%3}, [%4];" \
        : "=r"(r0), "=r"(r1), "=r"(r2), "=r"(r3) : "r"(addr))

#define MMA_E4M3(d0, d1, d2, d3, a0, a1, a2, a3, b0, b1) \
    asm volatile("mma.sync.aligned.m16n8k32.row.col.f32.e4m3.e4m3.f32 " \
        "{%0,%1,%2,%3}, {%4,%5,%6,%7}, {%8,%9}, {%0,%1,%2,%3};" \
        : "+f"(d0), "+f"(d1), "+f"(d2), "+f"(d3) \
        : "r"(a0), "r"(a1), "r"(a2), "r"(a3), "r"(b0), "r"(b1))

#define MMA_E4M3_ZC(d0, d1, d2, d3, a0, a1, a2, a3, b0, b1, z) \
    asm volatile("mma.sync.aligned.m16n8k32.row.col.f32.e4m3.e4m3.f32 " \
        "{%0,%1,%2,%3}, {%4,%5,%6,%7}, {%8,%9}, {%10,%10,%10,%10};" \
        : "=f"(d0), "=f"(d1), "=f"(d2), "=f"(d3) \
        : "r"(a0), "r"(a1), "r"(a2), "r"(a3), "r"(b0), "r"(b1), "f"(z))

// ============================================================================
// Weight canonicalization (harness upcasts fp8 inputs to f32; detect + cvt).
// Deterministic: every block tests the SAME first 4096 elements.
// ============================================================================
__global__ void conv_kernel(const void* w) {
    __shared__ int cnt;
    const int tid = threadIdx.x;
    if (tid == 0) cnt = 0;
    __syncthreads();
    const float* wf = (const float*)w;
    int ok = 0;
#pragma unroll
    for (int i = 0; i < 16; ++i) {
        float v = wf[tid + i * 256];
        if (isfinite(v) && fabsf(v) <= 1.0f) ok++;
    }
#pragma unroll
    for (int o = 16; o; o >>= 1) ok += __shfl_xor_sync(0xffffffffu, ok, o);
    if ((tid & 31) == 0) atomicAdd(&cnt, ok);
    __syncthreads();
    const bool is_f32 = (cnt >= 4000);

    const int i4 = blockIdx.x * 256 + tid;
    constexpr int TOT4 = NDIM * KDIM / 4;
    if (i4 >= TOT4) return;
    uint32_t outw;
    if (is_f32) {
        const float4 v = ((const float4*)w)[i4];
        unsigned short lo, hi;
        asm("cvt.rn.satfinite.e4m3x2.f32 %0, %1, %2;" : "=h"(lo) : "f"(v.y), "f"(v.x));
        asm("cvt.rn.satfinite.e4m3x2.f32 %0, %1, %2;" : "=h"(hi) : "f"(v.w), "f"(v.z));
        outw = (uint32_t)lo | ((uint32_t)hi << 16);
    } else {
        outw = ((const uint32_t*)w)[i4];
    }
    ((uint32_t*)g_w8)[i4] = outw;
}

// ============================================================================
// Fused GEMM: L2-prefetched act-quant + fp8 mma
// ============================================================================
__device__ __forceinline__ void issue_b(uint32_t sb, int tid, int kc, int st) {
    const int u = tid & 7;
    const int n0 = tid >> 3;
#pragma unroll
    for (int i = 0; i < 8; ++i) {
        const int n = n0 + i * 32;
        const uint32_t dst = sb + OFF_BS + st * 32768 + n * 128 + ((u ^ (n & 7)) * 16);
        const uint8_t* g = g_w8 + (size_t)n * KDIM + (size_t)kc * KC + u * 16;
        CP_ASYNC16(dst, g);
    }
    asm volatile("cp.async.commit_group;" ::: "memory");
}

// quant chunk kc into A stage st. 4 threads/row, 32 values (128B) each.
__device__ __forceinline__ void quant_chunk(const float* __restrict__ xq,
                                            float* __restrict__ SCm, uint32_t sb,
                                            int qrow, int qq, int kc, int st) {
    const float4* xp = (const float4*)(xq + (size_t)kc * KC);
    float4 v[8];
#pragma unroll
    for (int i = 0; i < 8; ++i) v[i] = xp[i];
    float am = 0.f;
#pragma unroll
    for (int i = 0; i < 8; ++i)
        am = fmaxf(am, fmaxf(fmaxf(fabsf(v[i].x), fabsf(v[i].y)),
                             fmaxf(fabsf(v[i].z), fabsf(v[i].w))));
    am = fmaxf(am, __shfl_xor_sync(0xffffffffu, am, 1));
    am = fmaxf(am, __shfl_xor_sync(0xffffffffu, am, 2));
    const float amax = fmaxf(am, 1e-8f);
    const float s = __fdiv_rn(amax, 448.0f);
    const float ri = __fdiv_rn(448.0f, amax);
    uint32_t wd[8];
#pragma unroll
    for (int i = 0; i < 8; ++i) {
        unsigned short lo, hi;
        asm("cvt.rn.satfinite.e4m3x2.f32 %0, %1, %2;"
            : "=h"(lo) : "f"(v[i].y * ri), "f"(v[i].x * ri));
        asm("cvt.rn.satfinite.e4m3x2.f32 %0, %1, %2;"
            : "=h"(hi) : "f"(v[i].w * ri), "f"(v[i].z * ri));
        wd[i] = (uint32_t)lo | ((uint32_t)hi << 16);
    }
    const uint32_t abase = sb + OFF_AS + st * 8192 + qrow * 128;
    const uint32_t u0 = (uint32_t)((qq * 2) ^ (qrow & 7));
    const uint32_t u1 = (uint32_t)((qq * 2 + 1) ^ (qrow & 7));
    asm volatile("st.shared.v4.b32 [%0], {%1,%2,%3,%4};"
        :: "r"(abase + u0 * 16), "r"(wd[0]), "r"(wd[1]), "r"(wd[2]), "r"(wd[3]) : "memory");
    asm volatile("st.shared.v4.b32 [%0], {%1,%2,%3,%4};"
        :: "r"(abase + u1 * 16), "r"(wd[4]), "r"(wd[5]), "r"(wd[6]), "r"(wd[7]) : "memory");
    if (qq == 0) SCm[st * 64 + qrow] = s;
}

__global__ void __launch_bounds__(NTH, 2)
fused_fp8_gemm(const float* __restrict__ x, const float* __restrict__ ws,
               float* __restrict__ out) {
    extern __shared__ char smem[];
    const uint32_t sb = smem_u32(smem);
    const int tid = threadIdx.x;
    const int lane = tid & 31;
    const int wid = tid >> 5;
    const size_t m0cta = (size_t)blockIdx.x * MT;

    if (tid < 112) ((float*)(smem + OFF_WS))[tid] = ws[tid];

    // quant role: 4 threads/row, 32 consecutive values (one 128B line) each
    const int qrow = tid >> 2;
    const int qq = tid & 3;
    const float* xq = x + (m0cta + qrow) * KDIM + qq * 32;

    // mma role: warp grid 2m x 4n, warp tile m32 x n64
    const int R0 = (wid >> 2) * 32;
    const int C0 = (wid & 3) * 64;
    const int nb = (wid & 3) >> 1;
    const int alane = lane & 15, asel = lane >> 4;
    const int nlane = (lane & 7) | ((lane >> 4) << 3);
    const int bsel = (lane >> 3) & 1;
    const int lr = lane >> 2;

    float acc[64];
#pragma unroll
    for (int i = 0; i < 64; ++i) acc[i] = 0.f;

    float* SCm = (float*)(smem + OFF_SC);
    const float* WS = (const float*)(smem + OFF_WS);

    // ---- prologue ----
    quant_chunk(xq, SCm, sb, qrow, qq, 0, 0);
    quant_chunk(xq, SCm, sb, qrow, qq, 1, 1);
    issue_b(sb, tid, 0, 0);
    issue_b(sb, tid, 1, 1);

#pragma unroll 1
    for (int kc = 0; kc < KB; ++kc) {
        const int st = kc & 1;
        if (kc == KB - 1) { asm volatile("cp.async.wait_group 0;" ::: "memory"); }
        else              { asm volatile("cp.async.wait_group 1;" ::: "memory"); }
        __syncthreads();

        // L2-prefetch x for chunk kc+2 (zero register cost; covered by MMA phase)
        if (kc + 2 < KB)
            asm volatile("prefetch.global.L2 [%0];" :: "l"(xq + (size_t)(kc + 2) * KC));

        const uint32_t ab = sb + OFF_AS + st * 8192;
        const uint32_t bb = sb + OFF_BS + st * 32768;
        const float wv = WS[nb * 56 + kc];
        float f[4];
#pragma unroll
        for (int mh = 0; mh < 2; ++mh) {
            f[mh * 2 + 0] = SCm[st * 64 + R0 + mh * 16 + lr] * wv;
            f[mh * 2 + 1] = SCm[st * 64 + R0 + mh * 16 + 8 + lr] * wv;
        }

        // B-fragment double buffer; step s = kh*8 + ng*2 + ks2 (16 steps)
        uint32_t bf[2][4];
        {
            const int nr = C0 + nlane;
            const uint32_t bd = bb + nr * 128 + ((bsel ^ (nr & 7)) * 16);
            LDMATRIX_X4(bf[0][0], bf[0][1], bf[0][2], bf[0][3], bd);
        }

#pragma unroll
        for (int kh = 0; kh < 2; ++kh) {
            uint32_t a[2][2][4];
#pragma unroll
            for (int ks2 = 0; ks2 < 2; ++ks2) {
#pragma unroll
                for (int mh = 0; mh < 2; ++mh) {
                    const int r = R0 + mh * 16 + alane;
                    const int ks = kh * 2 + ks2;
                    const uint32_t ad = ab + r * 128 + (((ks * 2 + asel) ^ (r & 7)) * 16);
                    LDMATRIX_X4(a[ks2][mh][0], a[ks2][mh][1], a[ks2][mh][2], a[ks2][mh][3], ad);
                }
            }

#pragma unroll
            for (int ng = 0; ng < 4; ++ng) {
                float p[16];
#pragma unroll
                for (int ks2 = 0; ks2 < 2; ++ks2) {
                    const int s = kh * 8 + ng * 2 + ks2;
                    const int buf = s & 1;
                    if (s < 15) {
                        const int sn = s + 1;
                        const int n_ng = (sn >> 1) & 3;
                        const int n_ks = ((sn >> 3) << 1) | (sn & 1);
                        const int nr = C0 + n_ng * 16 + nlane;
                        const uint32_t bd = bb + nr * 128 + (((n_ks * 2 + bsel) ^ (nr & 7)) * 16);
                        LDMATRIX_X4(bf[buf ^ 1][0], bf[buf ^ 1][1], bf[buf ^ 1][2], bf[buf ^ 1][3], bd);
                    }
                    if (ks2 == 0) {
#pragma unroll
                        for (int mh = 0; mh < 2; ++mh) {
                            MMA_E4M3_ZC(p[mh*8+0], p[mh*8+1], p[mh*8+2], p[mh*8+3],
                                        a[0][mh][0], a[0][mh][1], a[0][mh][2], a[0][mh][3],
                                        bf[buf][0], bf[buf][1], 0.f);
                            MMA_E4M3_ZC(p[mh*8+4], p[mh*8+5], p[mh*8+6], p[mh*8+7],
                                        a[0][mh][0], a[0][mh][1], a[0][mh][2], a[0][mh][3],
                                        bf[buf][2], bf[buf][3], 0.f);
                        }
                    } else {
#pragma unroll
                        for (int mh = 0; mh < 2; ++mh) {
                            MMA_E4M3(p[mh*8+0], p[mh*8+1], p[mh*8+2], p[mh*8+3],
                                     a[1][mh][0], a[1][mh][1], a[1][mh][2], a[1][mh][3],
                                     bf[buf][0], bf[buf][1]);
                            MMA_E4M3(p[mh*8+4], p[mh*8+5], p[mh*8+6], p[mh*8+7],
                                     a[1][mh][0], a[1][mh][1], a[1][mh][2], a[1][mh][3],
                                     bf[buf][2], bf[buf][3]);
                        }
                    }
                }
#pragma unroll
                for (int mh = 0; mh < 2; ++mh) {
#pragma unroll
                    for (int pr = 0; pr < 2; ++pr) {
                        const int pi = mh * 8 + pr * 4;
                        const int ai = ng * 16 + pi;
                        acc[ai+0] = fmaf(p[pi+0], f[mh*2+0], acc[ai+0]);
                        acc[ai+1] = fmaf(p[pi+1], f[mh*2+0], acc[ai+1]);
                        acc[ai+2] = fmaf(p[pi+2], f[mh*2+1], acc[ai+2]);
                        acc[ai+3] = fmaf(p[pi+3], f[mh*2+1], acc[ai+3]);
                    }
                }
            }
        }
        __syncthreads();

        // produce chunk kc+2 into the stage just freed (x loads hit L2)
        if (kc + 2 < KB) {
            quant_chunk(xq, SCm, sb, qrow, qq, kc + 2, st);
            issue_b(sb, tid, kc + 2, st);
        }
    }

    // ================= epilogue =================
#pragma unroll
    for (int mh = 0; mh < 2; ++mh) {
        const int row = R0 + mh * 16 + lr;
        float* o0 = out + (m0cta + row) * NDIM;
#pragma unroll
        for (int ng = 0; ng < 4; ++ng) {
#pragma unroll
            for (int pr = 0; pr < 2; ++pr) {
                const int base = ng * 16 + mh * 8 + pr * 4;
                const int col = C0 + ng * 16 + pr * 8 + (lane & 3) * 2;
                *(float2*)(o0 + col) = make_float2(acc[base], acc[base+1]);
                *(float2*)(o0 + 8 * NDIM + col) = make_float2(acc[base+2], acc[base+3]);
            }
        }
    }
}

// ============================================================================
extern "C" void kernel_launch(void* const* d_in, const int* in_sizes, int n_in,
                              void* d_out, int out_size) {
    const float* x = (const float*)d_in[0];
    const void* w = d_in[1];
    const float* ws = (const float*)d_in[2];
    float* out = (float*)d_out;

    const int M = in_sizes[0] / KDIM;       // 16384
    const int grid = M / MT;                // 256

    cudaFuncSetAttribute(fused_fp8_gemm, cudaFuncAttributeMaxDynamicSharedMemorySize, SMEM_TOTAL);

    conv_kernel<<<(NDIM * KDIM / 4 + 255) / 256, 256>>>(w);
    fused_fp8_gemm<<<grid, NTH, SMEM_TOTAL>>>(x, ws, out);
}